// round 1
// baseline (speedup 1.0000x reference)
#include <cuda_runtime.h>
#include <math.h>

#define B_  16
#define L_  1024
#define H_  8
#define E_  64
#define D_  512
#define LF  513
#define NF  1024

// ---------------- scratch (device globals; no allocations) ----------------
__device__ float  g_q2[B_*L_*D_];            // conv+GLU output, [B,L,D]
__device__ float2 g_qf[B_*H_*E_*LF];         // rfft(q2)
__device__ float2 g_kf[B_*H_*E_*LF];
__device__ float2 g_vf[B_*H_*E_*LF];
__device__ float2 g_of[B_*H_*E_*LF];         // scored output spectrum

// ======================= 1) Conv1d(d->2d,k=3) + GLU ========================
// y[b,o,l] = sum_{i,t} q[b, l+t-1, i] * W[o, i, t] + bias[o]; q2 = a*sigmoid(g)
#define CBL 32     // l-tile
#define CBO 32     // o-pair tile (o and o+512)
#define CKC 64     // K chunk over input channels

__global__ __launch_bounds__(256) void conv_glu_kernel(
    const float* __restrict__ q, const float* __restrict__ W,
    const float* __restrict__ bias)
{
    __shared__ float Xs[CBL+2][CKC+1];
    __shared__ float Wa[CBO][CKC*3+1];   // stride 193: conflict-free
    __shared__ float Wg[CBO][CKC*3+1];

    const int tid   = threadIdx.x;
    const int lbase = blockIdx.x * CBL;
    const int obase = blockIdx.y * CBO;
    const int b     = blockIdx.z;
    const int o_l   = tid & 31;        // output channel lane
    const int lg    = tid >> 5;        // 8 groups, 4 l each

    float acc_a[4], acc_g[4];
    const float ba = bias[obase + o_l];
    const float bg = bias[512 + obase + o_l];
    #pragma unroll
    for (int j = 0; j < 4; j++) { acc_a[j] = ba; acc_g[j] = bg; }

    for (int kc = 0; kc < D_; kc += CKC) {
        // stage X window [lbase-1, lbase+CBL] x CKC channels
        for (int idx = tid; idx < (CBL+2)*CKC; idx += 256) {
            int r = idx >> 6, kk = idx & 63;
            int row = lbase - 1 + r;
            float v = 0.f;
            if (row >= 0 && row < L_)
                v = q[(size_t)b*L_*D_ + (size_t)row*D_ + kc + kk];
            Xs[r][kk] = v;
        }
        // stage W chunk for both halves
        for (int idx = tid; idx < CBO*CKC*3; idx += 256) {
            int o = idx / 192, j = idx - o*192;
            size_t col = (size_t)kc*3 + j;
            Wa[o][j] = W[(size_t)(obase+o)*1536 + col];
            Wg[o][j] = W[(size_t)(512+obase+o)*1536 + col];
        }
        __syncthreads();

        #pragma unroll 4
        for (int kk = 0; kk < CKC; kk++) {
            float xv[6];
            #pragma unroll
            for (int r = 0; r < 6; r++) xv[r] = Xs[lg*4 + r][kk];
            #pragma unroll
            for (int t = 0; t < 3; t++) {
                float wa = Wa[o_l][kk*3+t];
                float wg = Wg[o_l][kk*3+t];
                #pragma unroll
                for (int j = 0; j < 4; j++) {
                    acc_a[j] = fmaf(xv[j+t], wa, acc_a[j]);
                    acc_g[j] = fmaf(xv[j+t], wg, acc_g[j]);
                }
            }
        }
        __syncthreads();
    }

    #pragma unroll
    for (int j = 0; j < 4; j++) {
        int l = lbase + lg*4 + j;
        float s = 1.f / (1.f + __expf(-acc_g[j]));
        g_q2[(size_t)b*L_*D_ + (size_t)l*D_ + obase + o_l] = acc_a[j] * s;
    }
}

// ======================= radix-2 FFT (1024-pt, smem) =======================
__device__ __forceinline__ void fft1024_smem(float* re, float* im,
                                             const float2* tw, int tid)
{
    for (int len = 2; len <= NF; len <<= 1) {
        int half  = len >> 1;
        int tstep = NF / len;
        for (int bi = tid; bi < NF/2; bi += 256) {
            int grp = bi / half;
            int pos = bi - grp*half;
            int i0 = grp*len + pos;
            int i1 = i0 + half;
            float2 w = tw[pos * tstep];           // exp(-2*pi*i * pos/len)
            float vr = re[i1], vi = im[i1];
            float tr = w.x*vr - w.y*vi;
            float ti = w.x*vi + w.y*vr;
            float ur = re[i0], ui = im[i0];
            re[i0] = ur + tr; im[i0] = ui + ti;
            re[i1] = ur - tr; im[i1] = ui - ti;
        }
        __syncthreads();
    }
}

// ======================= 2) rfft of q2 / k / v =============================
// blockIdx.x = b*512 + c (c = h*64+e), blockIdx.y selects tensor.
__global__ __launch_bounds__(256) void rfft_kernel(
    const float* __restrict__ kin, const float* __restrict__ vin)
{
    __shared__ float  sre[NF], sim[NF];
    __shared__ float2 tw[NF/2];
    const int tid = threadIdx.x;
    const int bc  = blockIdx.x;
    const int which = blockIdx.y;
    const float* src = (which == 0) ? g_q2 : ((which == 1) ? kin : vin);
    float2* dst = (which == 0) ? g_qf : ((which == 1) ? g_kf : g_vf);

    for (int j = tid; j < NF/2; j += 256) {
        float s, c;
        sincosf(-6.283185307179586f * (float)j / (float)NF, &s, &c);
        tw[j] = make_float2(c, s);
    }
    const float* x = src + (size_t)(bc >> 9)*L_*D_ + (bc & 511);
    for (int n = tid; n < NF; n += 256) {
        int r = __brev(n) >> 22;                 // 10-bit reverse
        sre[r] = x[(size_t)n * D_];
        sim[r] = 0.f;
    }
    __syncthreads();
    fft1024_smem(sre, sim, tw, tid);

    const float scale = 0.03125f;                // 1/sqrt(1024)
    for (int k = tid; k < LF; k += 256)
        dst[(size_t)bc*LF + k] = make_float2(sre[k]*scale, sim[k]*scale);
}

// ======================= 3) fused frequency attention ======================
// Per (b,h): s = (qf^T conj(kf))/8;  g=1+sigmoid(|s|);
// of = (sum_y s*g*vf) / max(sum_y |s|*g, 1e-12).  Single pass, no s tensor.
#define XT 32
#define YT 64

struct AttnSmem {
    float2 Qs[E_][XT+1];
    float2 Ks[E_][YT+1];
    float2 Vs[E_][YT+1];
    float2 Ss[XT][YT+1];
    float  rred[32][XT+1];
    float  rinv[XT];
};

__global__ __launch_bounds__(256) void attn_kernel()
{
    extern __shared__ char smem_raw[];
    AttnSmem& sm = *reinterpret_cast<AttnSmem*>(smem_raw);
    const int tid   = threadIdx.x;
    const int xbase = blockIdx.x * XT;
    const int bh    = blockIdx.y;

    const float2* qf = g_qf + (size_t)bh * E_ * LF;
    const float2* kf = g_kf + (size_t)bh * E_ * LF;
    const float2* vf = g_vf + (size_t)bh * E_ * LF;
    float2*       of = g_of + (size_t)bh * E_ * LF;

    // load Q tile, pre-scaled by 1/sqrt(E)=1/8
    for (int idx = tid; idx < E_*XT; idx += 256) {
        int e = idx >> 5, xx = idx & 31;
        int x = xbase + xx;
        float2 v = make_float2(0.f, 0.f);
        if (x < LF) { v = qf[(size_t)e*LF + x]; v.x *= 0.125f; v.y *= 0.125f; }
        sm.Qs[e][xx] = v;
    }

    const int tx  = tid & 7;    // phase1: 8 x-groups * 4 rows
    const int ty  = tid >> 3;   // phase1: 32 y-groups * 2 cols
    const int te  = tid & 15;   // phase2: 16 e-groups * 4
    const int tx2 = tid >> 4;   // phase2: 16 x-groups * 2

    float2 ofacc[4][2];
    #pragma unroll
    for (int a = 0; a < 4; a++)
        #pragma unroll
        for (int c = 0; c < 2; c++) ofacc[a][c] = make_float2(0.f, 0.f);
    float rsum[4] = {0.f, 0.f, 0.f, 0.f};

    for (int yt = 0; yt < 9; yt++) {           // 9*64 = 576 >= 513
        const int ybase = yt * YT;
        __syncthreads();                        // Ks/Vs/Ss safe to overwrite
        for (int idx = tid; idx < E_*YT; idx += 256) {
            int e = idx >> 6, yy = idx & 63;
            int y = ybase + yy;
            float2 kv = make_float2(0.f, 0.f), vv = make_float2(0.f, 0.f);
            if (y < LF) { kv = kf[(size_t)e*LF + y]; vv = vf[(size_t)e*LF + y]; }
            sm.Ks[e][yy] = kv;
            sm.Vs[e][yy] = vv;
        }
        __syncthreads();

        // ---- phase 1: s tile (complex, q * conj(k)) ----
        float sr[4][2], si[4][2];
        #pragma unroll
        for (int a = 0; a < 4; a++)
            #pragma unroll
            for (int c = 0; c < 2; c++) { sr[a][c] = 0.f; si[a][c] = 0.f; }

        #pragma unroll 2
        for (int e = 0; e < E_; e++) {
            float2 qv[4], kv[2];
            #pragma unroll
            for (int jx = 0; jx < 4; jx++) qv[jx] = sm.Qs[e][tx*4 + jx];
            #pragma unroll
            for (int jy = 0; jy < 2; jy++) kv[jy] = sm.Ks[e][ty*2 + jy];
            #pragma unroll
            for (int jx = 0; jx < 4; jx++)
                #pragma unroll
                for (int jy = 0; jy < 2; jy++) {
                    sr[jx][jy] = fmaf(qv[jx].x, kv[jy].x, sr[jx][jy]);
                    sr[jx][jy] = fmaf(qv[jx].y, kv[jy].y, sr[jx][jy]);
                    si[jx][jy] = fmaf(qv[jx].y, kv[jy].x, si[jx][jy]);
                    si[jx][jy] = fmaf(-qv[jx].x, kv[jy].y, si[jx][jy]);
                }
        }
        // gate: sc = s*(1+sigmoid(|s|));  rowsum += |s|*(1+sigmoid(|s|))
        #pragma unroll
        for (int jx = 0; jx < 4; jx++)
            #pragma unroll
            for (int jy = 0; jy < 2; jy++) {
                float re = sr[jx][jy], im = si[jx][jy];
                float m  = sqrtf(re*re + im*im);
                float g  = 1.f + 1.f / (1.f + __expf(-m));
                rsum[jx] += m * g;
                sm.Ss[tx*4 + jx][ty*2 + jy] = make_float2(re*g, im*g);
            }
        __syncthreads();

        // ---- phase 2: of += Ss * Vs^T (complex) ----
        #pragma unroll 2
        for (int y = 0; y < YT; y++) {
            float2 vv[4], sv[2];
            #pragma unroll
            for (int je = 0; je < 4; je++) vv[je] = sm.Vs[te*4 + je][y];
            #pragma unroll
            for (int jx = 0; jx < 2; jx++) sv[jx] = sm.Ss[tx2*2 + jx][y];
            #pragma unroll
            for (int je = 0; je < 4; je++)
                #pragma unroll
                for (int jx = 0; jx < 2; jx++) {
                    ofacc[je][jx].x = fmaf(sv[jx].x, vv[je].x, ofacc[je][jx].x);
                    ofacc[je][jx].x = fmaf(-sv[jx].y, vv[je].y, ofacc[je][jx].x);
                    ofacc[je][jx].y = fmaf(sv[jx].x, vv[je].y, ofacc[je][jx].y);
                    ofacc[je][jx].y = fmaf(sv[jx].y, vv[je].x, ofacc[je][jx].y);
                }
        }
    }

    // reduce rowsum over the 32 y-groups
    __syncthreads();
    #pragma unroll
    for (int jx = 0; jx < 4; jx++) sm.rred[ty][tx*4 + jx] = rsum[jx];
    __syncthreads();
    if (tid < XT) {
        float t = 0.f;
        #pragma unroll 8
        for (int r = 0; r < 32; r++) t += sm.rred[r][tid];
        sm.rinv[tid] = 1.f / fmaxf(t, 1e-12f);
    }
    __syncthreads();

    #pragma unroll
    for (int je = 0; je < 4; je++)
        #pragma unroll
        for (int jx = 0; jx < 2; jx++) {
            int e  = te*4 + je;
            int xx = tx2*2 + jx;
            int x  = xbase + xx;
            if (x < LF) {
                float ri = sm.rinv[xx];
                of[(size_t)e*LF + x] =
                    make_float2(ofacc[je][jx].x * ri, ofacc[je][jx].y * ri);
            }
        }
}

// ======================= 4) irfft (conj trick) + transpose =================
__global__ __launch_bounds__(256) void irfft_kernel(float* __restrict__ out)
{
    __shared__ float  sre[NF], sim[NF];
    __shared__ float2 tw[NF/2];
    const int tid = threadIdx.x;
    const int bc  = blockIdx.x;                 // b*512 + c
    const float2* ofp = g_of + (size_t)bc * LF;

    for (int j = tid; j < NF/2; j += 256) {
        float s, c;
        sincosf(-6.283185307179586f * (float)j / (float)NF, &s, &c);
        tw[j] = make_float2(c, s);
    }
    // spectrum s[k] = conj(Xfull[k]); Xfull hermitian from of[0..512]
    for (int n = tid; n < NF; n += 256) {
        int k = (n <= 512) ? n : NF - n;
        float2 X = ofp[k];
        float re = X.x;
        float im = (n <= 512) ? -X.y : X.y;
        int r = __brev(n) >> 22;
        sre[r] = re; sim[r] = im;
    }
    __syncthreads();
    fft1024_smem(sre, sim, tw, tid);

    // out[b,l,h,e]: x[n] = Re(Y[n]) / sqrt(N)
    float* o = out + (size_t)(bc >> 9)*L_*D_ + (bc & 511);
    for (int n = tid; n < NF; n += 256)
        o[(size_t)n * D_] = sre[n] * 0.03125f;
}

// ============================== launcher ===================================
extern "C" void kernel_launch(void* const* d_in, const int* in_sizes, int n_in,
                              void* d_out, int out_size)
{
    const float* q    = (const float*)d_in[0];
    const float* k    = (const float*)d_in[1];
    const float* v    = (const float*)d_in[2];
    const float* W    = (const float*)d_in[3];
    const float* bias = (const float*)d_in[4];
    float* out = (float*)d_out;

    cudaFuncSetAttribute(attn_kernel,
        cudaFuncAttributeMaxDynamicSharedMemorySize, (int)sizeof(AttnSmem));

    conv_glu_kernel<<<dim3(L_/CBL, D_/CBO, B_), 256>>>(q, W, bias);
    rfft_kernel<<<dim3(B_*D_, 3), 256>>>(k, v);
    attn_kernel<<<dim3((LF + XT - 1)/XT, B_*H_), 256, sizeof(AttnSmem)>>>();
    irfft_kernel<<<B_*D_, 256>>>(out);
}

// round 5
// speedup vs baseline: 1.2824x; 1.2824x over previous
#include <cuda_runtime.h>
#include <math.h>
#include <stdint.h>

#define B_  16
#define L_  1024
#define H_  8
#define E_  64
#define D_  512
#define LF  513
#define NF  1024
#define QN  (B_*L_*D_)
#define WN  (1024*512*3)

// ---------------- scratch (device globals; no allocations) ----------------
__device__ float  g_qr[QN];                  // tf32-rounded q
__device__ float  g_Wr[WN];                  // tf32-rounded W
__device__ float  g_q2[B_*L_*D_];            // conv+GLU output, [B,L,D]
__device__ float2 g_qf[B_*H_*E_*LF];
__device__ float2 g_kf[B_*H_*E_*LF];
__device__ float2 g_vf[B_*H_*E_*LF];
__device__ float2 g_of[B_*H_*E_*LF];

// ======================= helpers ==========================================
__device__ __forceinline__ uint32_t smem_u32(const void* p) {
    uint32_t a;
    asm("{ .reg .u64 t; cvta.to.shared.u64 t, %1; cvt.u32.u64 %0, t; }"
        : "=r"(a) : "l"(p));
    return a;
}
__device__ __forceinline__ float tf32r(float x) {   // round-to-nearest tf32
    float y; asm("cvt.rna.tf32.f32 %0, %1;" : "=f"(y) : "f"(x)); return y;
}

#define MMA_TF32(c, a, b0v, b1v) \
    asm volatile("mma.sync.aligned.m16n8k8.row.col.f32.tf32.tf32.f32 " \
        "{%0,%1,%2,%3}, {%4,%5,%6,%7}, {%8,%9}, {%0,%1,%2,%3};" \
        : "+f"((c)[0]), "+f"((c)[1]), "+f"((c)[2]), "+f"((c)[3]) \
        : "r"((a)[0]), "r"((a)[1]), "r"((a)[2]), "r"((a)[3]), \
          "r"(b0v), "r"(b1v))

// ======================= 0) pre-round q and W to tf32 ======================
__global__ __launch_bounds__(256) void preround_kernel(
    const float* __restrict__ q, const float* __restrict__ W)
{
    int i0 = blockIdx.x * blockDim.x + threadIdx.x;
    int stride = gridDim.x * blockDim.x;
    for (int i = i0; i < QN; i += stride) g_qr[i] = tf32r(q[i]);
    for (int i = i0; i < WN; i += stride) g_Wr[i] = tf32r(W[i]);
}

// ======================= 1) Conv1d+GLU via mma.sync tf32 ==================
// GEMM: C[m=(b,l), n] = sum_k A[m,k]*B[n,k],  k=(i,t) im2col, K=1536.
// n interleaved: even n -> a-half (o=obase+n/2), odd n -> g-half (o+512).
// Per block: 128 m-rows x 128 n-cols (= 64 output channels, a&g).
// SMEM: A[2][128][36], B[2][128][36] floats (stride 36 -> conflict-free frags,
// 144B rows keep 16B cp.async alignment).
#define CONV_SMEM (18432*4)

__global__ __launch_bounds__(256) void conv_mma_kernel(
    const float* __restrict__ bias, float* __restrict__ q2out)
{
    extern __shared__ float smf[];
    const int tid  = threadIdx.x;
    const int wid  = tid >> 5;
    const int lane = tid & 31;
    const int gid  = lane >> 2;          // 0..7
    const int tg   = lane & 3;           // 0..3
    const int mw   = wid & 3;            // 4 m-sections of 32
    const int nw   = wid >> 2;           // 2 n-sections of 64
    const int mtile = blockIdx.x;        // 0..127
    const int obase = blockIdx.y * 64;   // 0..448
    const int b  = mtile >> 3;
    const int l0 = (mtile & 7) * 128;
    const uint32_t sb = smem_u32(smf);
    const float* qb = g_qr + (size_t)b * L_ * D_;

    float C[2][8][4];
    #pragma unroll
    for (int mf = 0; mf < 2; ++mf)
        #pragma unroll
        for (int j = 0; j < 8; ++j)
            #pragma unroll
            for (int u = 0; u < 4; ++u) C[mf][j][u] = 0.f;

    // ---- async stage of one K-chunk (32 k) into buffer bf ----
    auto issue = [&](int c, int bf) {
        // A: 128 x 32, im2col gather (4B cp.async, zfill OOB)
        #pragma unroll
        for (int j = 0; j < 16; ++j) {
            int linear = j * 256 + tid;
            int m  = linear & 127;
            int kk = linear >> 7;
            int k  = c * 32 + kk;
            int i  = k / 3;
            int t  = k - 3 * i;
            int lt = l0 + m + t - 1;
            int ltc = lt < 0 ? 0 : (lt > L_-1 ? L_-1 : lt);
            const float* src = qb + (size_t)ltc * D_ + i;
            int ss = (lt >= 0 && lt < L_) ? 4 : 0;
            uint32_t sa = sb + (uint32_t)(bf*4608 + m*36 + kk) * 4;
            asm volatile("cp.async.ca.shared.global [%0], [%1], 4, %2;"
                         :: "r"(sa), "l"(src), "r"(ss));
        }
        // B: 128 n-rows x 32 k (16B cp.async), n interleaved a/g
        #pragma unroll
        for (int j = 0; j < 4; ++j) {
            int linear = j * 256 + tid;
            int n   = linear >> 3;
            int kk4 = linear & 7;
            int grow = ((n & 1) ? 512 : 0) + obase + (n >> 1);
            const float* src = g_Wr + (size_t)grow * 1536 + c * 32 + kk4 * 4;
            uint32_t sa = sb + (uint32_t)(9216 + bf*4608 + n*36 + kk4*4) * 4;
            asm volatile("cp.async.ca.shared.global [%0], [%1], 16, 16;"
                         :: "r"(sa), "l"(src));
        }
        asm volatile("cp.async.commit_group;");
    };

    issue(0, 0);
    for (int c = 0; c < 48; ++c) {
        const int bf = c & 1;
        if (c + 1 < 48) {
            issue(c + 1, bf ^ 1);
            asm volatile("cp.async.wait_group 1;");
        } else {
            asm volatile("cp.async.wait_group 0;");
        }
        __syncthreads();

        const float* Abase = smf + bf*4608;
        const float* Bbase = smf + 9216 + bf*4608;
        #pragma unroll
        for (int k8 = 0; k8 < 4; ++k8) {
            uint32_t af[2][4];
            #pragma unroll
            for (int mf = 0; mf < 2; ++mf) {
                const float* Ap = Abase + (mw*32 + mf*16 + gid)*36 + k8*8;
                af[mf][0] = __float_as_uint(Ap[tg]);
                af[mf][1] = __float_as_uint(Ap[8*36 + tg]);
                af[mf][2] = __float_as_uint(Ap[tg + 4]);
                af[mf][3] = __float_as_uint(Ap[8*36 + tg + 4]);
            }
            #pragma unroll
            for (int j = 0; j < 8; ++j) {
                const float* Bp = Bbase + (nw*64 + j*8 + gid)*36 + k8*8;
                uint32_t b0 = __float_as_uint(Bp[tg]);
                uint32_t b1 = __float_as_uint(Bp[tg + 4]);
                MMA_TF32(C[0][j], af[0], b0, b1);
                MMA_TF32(C[1][j], af[1], b0, b1);
            }
        }
        __syncthreads();
    }

    // ---- epilogue: GLU (c0=a, c1=g per fragment column pair) ----
    #pragma unroll
    for (int mf = 0; mf < 2; ++mf) {
        int r0 = mtile*128 + mw*32 + mf*16 + gid;
        #pragma unroll
        for (int j = 0; j < 8; ++j) {
            int och = obase + nw*32 + j*4 + tg;
            float ba = bias[och], bg = bias[512 + och];
            float a0 = C[mf][j][0] + ba, g0 = C[mf][j][1] + bg;
            float a1 = C[mf][j][2] + ba, g1 = C[mf][j][3] + bg;
            q2out[(size_t)r0*D_ + och]       = a0 / (1.f + __expf(-g0));
            q2out[(size_t)(r0+8)*D_ + och]   = a1 / (1.f + __expf(-g1));
        }
    }
}

// ======================= radix-2 FFT (1024-pt, smem) =======================
__device__ __forceinline__ void fft1024_smem(float* re, float* im,
                                             const float2* tw, int tid)
{
    for (int len = 2; len <= NF; len <<= 1) {
        int half  = len >> 1;
        int tstep = NF / len;
        for (int bi = tid; bi < NF/2; bi += 256) {
            int grp = bi / half;
            int pos = bi - grp*half;
            int i0 = grp*len + pos;
            int i1 = i0 + half;
            float2 w = tw[pos * tstep];
            float vr = re[i1], vi = im[i1];
            float tr = w.x*vr - w.y*vi;
            float ti = w.x*vi + w.y*vr;
            float ur = re[i0], ui = im[i0];
            re[i0] = ur + tr; im[i0] = ui + ti;
            re[i1] = ur - tr; im[i1] = ui - ti;
        }
        __syncthreads();
    }
}

// ============== 2a) rfft of k & v packed: z = k + i*v ======================
__global__ __launch_bounds__(256) void rfft_kv_kernel(
    const float* __restrict__ kin, const float* __restrict__ vin)
{
    __shared__ float  sre[NF], sim[NF];
    __shared__ float2 tw[NF/2];
    const int tid = threadIdx.x;
    const int bc  = blockIdx.x;              // b*512 + c
    for (int j = tid; j < NF/2; j += 256) {
        float s, c;
        sincosf(-6.283185307179586f * (float)j / (float)NF, &s, &c);
        tw[j] = make_float2(c, s);
    }
    const float* kp = kin + (size_t)(bc >> 9)*L_*D_ + (bc & 511);
    const float* vp = vin + (size_t)(bc >> 9)*L_*D_ + (bc & 511);
    for (int n = tid; n < NF; n += 256) {
        int r = __brev(n) >> 22;
        sre[r] = kp[(size_t)n * D_];
        sim[r] = vp[(size_t)n * D_];
    }
    __syncthreads();
    fft1024_smem(sre, sim, tw, tid);

    const float sc_ = 0.03125f;
    float2* kf = g_kf + (size_t)bc * LF;
    float2* vf = g_vf + (size_t)bc * LF;
    for (int x = tid; x < LF; x += 256) {
        int xm = (NF - x) & (NF - 1);
        float Pr = sre[x], Pi = sim[x], Qr = sre[xm], Qi = sim[xm];
        kf[x] = make_float2(0.5f*(Pr + Qr)*sc_, 0.5f*(Pi - Qi)*sc_);
        vf[x] = make_float2(0.5f*(Pi + Qi)*sc_, 0.5f*(Qr - Pr)*sc_);
    }
}

// ============== 2b) rfft of q2 packed channel pairs ========================
__global__ __launch_bounds__(256) void rfft_q_kernel()
{
    __shared__ float  sre[NF], sim[NF];
    __shared__ float2 tw[NF/2];
    const int tid = threadIdx.x;
    const int bc2 = blockIdx.x;              // b*256 + pair
    const int b   = bc2 >> 8;
    const int c0  = (bc2 & 255) * 2;
    for (int j = tid; j < NF/2; j += 256) {
        float s, c;
        sincosf(-6.283185307179586f * (float)j / (float)NF, &s, &c);
        tw[j] = make_float2(c, s);
    }
    const float* q0 = g_q2 + (size_t)b*L_*D_ + c0;
    for (int n = tid; n < NF; n += 256) {
        int r = __brev(n) >> 22;
        sre[r] = q0[(size_t)n * D_];
        sim[r] = q0[(size_t)n * D_ + 1];
    }
    __syncthreads();
    fft1024_smem(sre, sim, tw, tid);

    const float sc_ = 0.03125f;
    float2* f0 = g_qf + (size_t)(b*512 + c0) * LF;
    float2* f1 = f0 + LF;
    for (int x = tid; x < LF; x += 256) {
        int xm = (NF - x) & (NF - 1);
        float Pr = sre[x], Pi = sim[x], Qr = sre[xm], Qi = sim[xm];
        f0[x] = make_float2(0.5f*(Pr + Qr)*sc_, 0.5f*(Pi - Qi)*sc_);
        f1[x] = make_float2(0.5f*(Pi + Qi)*sc_, 0.5f*(Qr - Pr)*sc_);
    }
}

// ======================= 3) fused frequency attention ======================
#define XT 32
#define YT 64

struct AttnSmem {
    float2 Qs[E_][XT+1];
    float2 Ks[E_][YT+1];
    float2 Vs[E_][YT+1];
    float2 Ss[XT][YT+1];
    float  rred[32][XT+1];
    float  rinv[XT];
};

__global__ __launch_bounds__(256) void attn_kernel()
{
    extern __shared__ char smem_raw[];
    AttnSmem& sm = *reinterpret_cast<AttnSmem*>(smem_raw);
    const int tid   = threadIdx.x;
    const int xbase = blockIdx.x * XT;
    const int bh    = blockIdx.y;

    const float2* qf = g_qf + (size_t)bh * E_ * LF;
    const float2* kf = g_kf + (size_t)bh * E_ * LF;
    const float2* vf = g_vf + (size_t)bh * E_ * LF;
    float2*       of = g_of + (size_t)bh * E_ * LF;

    for (int idx = tid; idx < E_*XT; idx += 256) {
        int e = idx >> 5, xx = idx & 31;
        int x = xbase + xx;
        float2 v = make_float2(0.f, 0.f);
        if (x < LF) { v = qf[(size_t)e*LF + x]; v.x *= 0.125f; v.y *= 0.125f; }
        sm.Qs[e][xx] = v;
    }

    const int tx  = tid & 7;
    const int ty  = tid >> 3;
    const int te  = tid & 15;
    const int tx2 = tid >> 4;

    float2 ofacc[4][2];
    #pragma unroll
    for (int a = 0; a < 4; a++)
        #pragma unroll
        for (int c = 0; c < 2; c++) ofacc[a][c] = make_float2(0.f, 0.f);
    float rsum[4] = {0.f, 0.f, 0.f, 0.f};

    for (int yt = 0; yt < 9; yt++) {
        const int ybase = yt * YT;
        __syncthreads();
        for (int idx = tid; idx < E_*YT; idx += 256) {
            int e = idx >> 6, yy = idx & 63;
            int y = ybase + yy;
            float2 kv = make_float2(0.f, 0.f), vv = make_float2(0.f, 0.f);
            if (y < LF) { kv = kf[(size_t)e*LF + y]; vv = vf[(size_t)e*LF + y]; }
            sm.Ks[e][yy] = kv;
            sm.Vs[e][yy] = vv;
        }
        __syncthreads();

        float sr[4][2], si[4][2];
        #pragma unroll
        for (int a = 0; a < 4; a++)
            #pragma unroll
            for (int c = 0; c < 2; c++) { sr[a][c] = 0.f; si[a][c] = 0.f; }

        #pragma unroll 2
        for (int e = 0; e < E_; e++) {
            float2 qv[4], kv[2];
            #pragma unroll
            for (int jx = 0; jx < 4; jx++) qv[jx] = sm.Qs[e][tx*4 + jx];
            #pragma unroll
            for (int jy = 0; jy < 2; jy++) kv[jy] = sm.Ks[e][ty*2 + jy];
            #pragma unroll
            for (int jx = 0; jx < 4; jx++)
                #pragma unroll
                for (int jy = 0; jy < 2; jy++) {
                    sr[jx][jy] = fmaf(qv[jx].x, kv[jy].x, sr[jx][jy]);
                    sr[jx][jy] = fmaf(qv[jx].y, kv[jy].y, sr[jx][jy]);
                    si[jx][jy] = fmaf(qv[jx].y, kv[jy].x, si[jx][jy]);
                    si[jx][jy] = fmaf(-qv[jx].x, kv[jy].y, si[jx][jy]);
                }
        }
        #pragma unroll
        for (int jx = 0; jx < 4; jx++)
            #pragma unroll
            for (int jy = 0; jy < 2; jy++) {
                float re = sr[jx][jy], im = si[jx][jy];
                float m  = sqrtf(re*re + im*im);
                float g  = 1.f + 1.f / (1.f + __expf(-m));
                rsum[jx] += m * g;
                sm.Ss[tx*4 + jx][ty*2 + jy] = make_float2(re*g, im*g);
            }
        __syncthreads();

        #pragma unroll 2
        for (int y = 0; y < YT; y++) {
            float2 vv[4], sv[2];
            #pragma unroll
            for (int je = 0; je < 4; je++) vv[je] = sm.Vs[te*4 + je][y];
            #pragma unroll
            for (int jx = 0; jx < 2; jx++) sv[jx] = sm.Ss[tx2*2 + jx][y];
            #pragma unroll
            for (int je = 0; je < 4; je++)
                #pragma unroll
                for (int jx = 0; jx < 2; jx++) {
                    ofacc[je][jx].x = fmaf(sv[jx].x, vv[je].x, ofacc[je][jx].x);
                    ofacc[je][jx].x = fmaf(-sv[jx].y, vv[je].y, ofacc[je][jx].x);
                    ofacc[je][jx].y = fmaf(sv[jx].x, vv[je].y, ofacc[je][jx].y);
                    ofacc[je][jx].y = fmaf(sv[jx].y, vv[je].x, ofacc[je][jx].y);
                }
        }
    }

    __syncthreads();
    #pragma unroll
    for (int jx = 0; jx < 4; jx++) sm.rred[ty][tx*4 + jx] = rsum[jx];
    __syncthreads();
    if (tid < XT) {
        float t = 0.f;
        #pragma unroll 8
        for (int r = 0; r < 32; r++) t += sm.rred[r][tid];
        sm.rinv[tid] = 1.f / fmaxf(t, 1e-12f);
    }
    __syncthreads();

    #pragma unroll
    for (int je = 0; je < 4; je++)
        #pragma unroll
        for (int jx = 0; jx < 2; jx++) {
            int e  = te*4 + je;
            int xx = tx2*2 + jx;
            int x  = xbase + xx;
            if (x < LF) {
                float ri = sm.rinv[xx];
                of[(size_t)e*LF + x] =
                    make_float2(ofacc[je][jx].x * ri, ofacc[je][jx].y * ri);
            }
        }
}

// ======================= 4) irfft packed channel pairs =====================
// irfft ignores Im at bins 0 and 512 — zero them so each channel's
// anti-hermitian residue doesn't leak into its pair partner.
__global__ __launch_bounds__(256) void irfft_kernel(float* __restrict__ out)
{
    __shared__ float  sre[NF], sim[NF];
    __shared__ float2 tw[NF/2];
    const int tid = threadIdx.x;
    const int bc2 = blockIdx.x;              // b*256 + pair
    const int b   = bc2 >> 8;
    const int c0  = (bc2 & 255) * 2;
    const float2* o0 = g_of + (size_t)(b*512 + c0) * LF;
    const float2* o1 = o0 + LF;

    for (int j = tid; j < NF/2; j += 256) {
        float s, c;
        sincosf(-6.283185307179586f * (float)j / (float)NF, &s, &c);
        tw[j] = make_float2(c, s);
    }
    for (int n = tid; n < NF; n += 256) {
        int k2 = (n <= 512) ? n : NF - n;
        float sg = (n <= 512) ? 1.f : -1.f;
        float zf = (k2 == 0 || k2 == 512) ? 0.f : 1.f;
        float2 A0 = o0[k2], A1 = o1[k2];
        A0.y *= zf; A1.y *= zf;
        float cre = A0.x - sg * A1.y;
        float cim = -sg * A0.y - A1.x;
        int r = __brev(n) >> 22;
        sre[r] = cre; sim[r] = cim;
    }
    __syncthreads();
    fft1024_smem(sre, sim, tw, tid);

    float* op = out + (size_t)b*L_*D_ + c0;
    for (int n = tid; n < NF; n += 256) {
        op[(size_t)n * D_]     =  sre[n] * 0.03125f;
        op[(size_t)n * D_ + 1] = -sim[n] * 0.03125f;
    }
}

// ============================== launcher ===================================
extern "C" void kernel_launch(void* const* d_in, const int* in_sizes, int n_in,
                              void* d_out, int out_size)
{
    const float* q    = (const float*)d_in[0];
    const float* k    = (const float*)d_in[1];
    const float* v    = (const float*)d_in[2];
    const float* W    = (const float*)d_in[3];
    const float* bias = (const float*)d_in[4];
    float* out = (float*)d_out;

    float* q2p;
    cudaGetSymbolAddress((void**)&q2p, g_q2);

    cudaFuncSetAttribute(conv_mma_kernel,
        cudaFuncAttributeMaxDynamicSharedMemorySize, CONV_SMEM);
    cudaFuncSetAttribute(attn_kernel,
        cudaFuncAttributeMaxDynamicSharedMemorySize, (int)sizeof(AttnSmem));

    preround_kernel<<<4096, 256>>>(q, W);
    conv_mma_kernel<<<dim3(128, 8), 256, CONV_SMEM>>>(bias, q2p);
    rfft_kv_kernel<<<B_*D_, 256>>>(k, v);
    rfft_q_kernel<<<B_*256, 256>>>();
    attn_kernel<<<dim3((LF + XT - 1)/XT, B_*H_), 256, sizeof(AttnSmem)>>>();
    irfft_kernel<<<B_*256, 256>>>(out);
}

// round 6
// speedup vs baseline: 1.3906x; 1.0843x over previous
#include <cuda_runtime.h>
#include <math.h>
#include <stdint.h>

#define B_  16
#define L_  1024
#define H_  8
#define E_  64
#define D_  512
#define LF  513
#define NF  1024
#define QN  (B_*L_*D_)
#define WN  (1024*512*3)

// ---------------- scratch (device globals; no allocations) ----------------
__device__ float  g_qr[QN];                  // tf32-rounded q
__device__ float  g_Wr[WN];                  // tf32-rounded W
__device__ float  g_q2[B_*L_*D_];            // conv+GLU output, [B,L,D]
__device__ float2 g_qf[B_*H_*E_*LF];
__device__ float2 g_kf[B_*H_*E_*LF];
__device__ float2 g_vf[B_*H_*E_*LF];
__device__ float2 g_of[B_*H_*E_*LF];

// ======================= helpers ==========================================
__device__ __forceinline__ uint32_t smem_u32(const void* p) {
    uint32_t a;
    asm("{ .reg .u64 t; cvta.to.shared.u64 t, %1; cvt.u32.u64 %0, t; }"
        : "=r"(a) : "l"(p));
    return a;
}
__device__ __forceinline__ float tf32r(float x) {   // round-to-nearest tf32
    float y; asm("cvt.rna.tf32.f32 %0, %1;" : "=f"(y) : "f"(x)); return y;
}
__device__ __forceinline__ float sqrt_ap(float x) {
    float y; asm("sqrt.approx.f32 %0, %1;" : "=f"(y) : "f"(x)); return y;
}
__device__ __forceinline__ float tanh_ap(float x) {
    float y; asm("tanh.approx.f32 %0, %1;" : "=f"(y) : "f"(x)); return y;
}

#define MMA_TF32(c, a, b0v, b1v) \
    asm volatile("mma.sync.aligned.m16n8k8.row.col.f32.tf32.tf32.f32 " \
        "{%0,%1,%2,%3}, {%4,%5,%6,%7}, {%8,%9}, {%0,%1,%2,%3};" \
        : "+f"((c)[0]), "+f"((c)[1]), "+f"((c)[2]), "+f"((c)[3]) \
        : "r"((a)[0]), "r"((a)[1]), "r"((a)[2]), "r"((a)[3]), \
          "r"(b0v), "r"(b1v))

// ======================= 0) pre-round q and W to tf32 ======================
__global__ __launch_bounds__(256) void preround_kernel(
    const float* __restrict__ q, const float* __restrict__ W)
{
    int i0 = blockIdx.x * blockDim.x + threadIdx.x;
    int stride = gridDim.x * blockDim.x;
    for (int i = i0; i < QN; i += stride) g_qr[i] = tf32r(q[i]);
    for (int i = i0; i < WN; i += stride) g_Wr[i] = tf32r(W[i]);
}

// ======================= 1) Conv1d+GLU via mma.sync tf32 ==================
#define CONV_SMEM (18432*4)

__global__ __launch_bounds__(256) void conv_mma_kernel(
    const float* __restrict__ bias, float* __restrict__ q2out)
{
    extern __shared__ float smf[];
    const int tid  = threadIdx.x;
    const int wid  = tid >> 5;
    const int lane = tid & 31;
    const int gid  = lane >> 2;          // 0..7
    const int tg   = lane & 3;           // 0..3
    const int mw   = wid & 3;            // 4 m-sections of 32
    const int nw   = wid >> 2;           // 2 n-sections of 64
    const int mtile = blockIdx.x;        // 0..127
    const int obase = blockIdx.y * 64;   // 0..448
    const int b  = mtile >> 3;
    const int l0 = (mtile & 7) * 128;
    const uint32_t sb = smem_u32(smf);
    const float* qb = g_qr + (size_t)b * L_ * D_;

    float C[2][8][4];
    #pragma unroll
    for (int mf = 0; mf < 2; ++mf)
        #pragma unroll
        for (int j = 0; j < 8; ++j)
            #pragma unroll
            for (int u = 0; u < 4; ++u) C[mf][j][u] = 0.f;

    auto issue = [&](int c, int bf) {
        #pragma unroll
        for (int j = 0; j < 16; ++j) {
            int linear = j * 256 + tid;
            int m  = linear & 127;
            int kk = linear >> 7;
            int k  = c * 32 + kk;
            int i  = k / 3;
            int t  = k - 3 * i;
            int lt = l0 + m + t - 1;
            int ltc = lt < 0 ? 0 : (lt > L_-1 ? L_-1 : lt);
            const float* src = qb + (size_t)ltc * D_ + i;
            int ss = (lt >= 0 && lt < L_) ? 4 : 0;
            uint32_t sa = sb + (uint32_t)(bf*4608 + m*36 + kk) * 4;
            asm volatile("cp.async.ca.shared.global [%0], [%1], 4, %2;"
                         :: "r"(sa), "l"(src), "r"(ss));
        }
        #pragma unroll
        for (int j = 0; j < 4; ++j) {
            int linear = j * 256 + tid;
            int n   = linear >> 3;
            int kk4 = linear & 7;
            int grow = ((n & 1) ? 512 : 0) + obase + (n >> 1);
            const float* src = g_Wr + (size_t)grow * 1536 + c * 32 + kk4 * 4;
            uint32_t sa = sb + (uint32_t)(9216 + bf*4608 + n*36 + kk4*4) * 4;
            asm volatile("cp.async.ca.shared.global [%0], [%1], 16, 16;"
                         :: "r"(sa), "l"(src));
        }
        asm volatile("cp.async.commit_group;");
    };

    issue(0, 0);
    for (int c = 0; c < 48; ++c) {
        const int bf = c & 1;
        if (c + 1 < 48) {
            issue(c + 1, bf ^ 1);
            asm volatile("cp.async.wait_group 1;");
        } else {
            asm volatile("cp.async.wait_group 0;");
        }
        __syncthreads();

        const float* Abase = smf + bf*4608;
        const float* Bbase = smf + 9216 + bf*4608;
        #pragma unroll
        for (int k8 = 0; k8 < 4; ++k8) {
            uint32_t af[2][4];
            #pragma unroll
            for (int mf = 0; mf < 2; ++mf) {
                const float* Ap = Abase + (mw*32 + mf*16 + gid)*36 + k8*8;
                af[mf][0] = __float_as_uint(Ap[tg]);
                af[mf][1] = __float_as_uint(Ap[8*36 + tg]);
                af[mf][2] = __float_as_uint(Ap[tg + 4]);
                af[mf][3] = __float_as_uint(Ap[8*36 + tg + 4]);
            }
            #pragma unroll
            for (int j = 0; j < 8; ++j) {
                const float* Bp = Bbase + (nw*64 + j*8 + gid)*36 + k8*8;
                uint32_t b0 = __float_as_uint(Bp[tg]);
                uint32_t b1 = __float_as_uint(Bp[tg + 4]);
                MMA_TF32(C[0][j], af[0], b0, b1);
                MMA_TF32(C[1][j], af[1], b0, b1);
            }
        }
        __syncthreads();
    }

    #pragma unroll
    for (int mf = 0; mf < 2; ++mf) {
        int r0 = mtile*128 + mw*32 + mf*16 + gid;
        #pragma unroll
        for (int j = 0; j < 8; ++j) {
            int och = obase + nw*32 + j*4 + tg;
            float ba = bias[och], bg = bias[512 + och];
            float a0 = C[mf][j][0] + ba, g0 = C[mf][j][1] + bg;
            float a1 = C[mf][j][2] + ba, g1 = C[mf][j][3] + bg;
            q2out[(size_t)r0*D_ + och]       = a0 / (1.f + __expf(-g0));
            q2out[(size_t)(r0+8)*D_ + och]   = a1 / (1.f + __expf(-g1));
        }
    }
}

// ======================= radix-2 FFT (1024-pt, smem) =======================
__device__ __forceinline__ void fft1024_smem(float* re, float* im,
                                             const float2* tw, int tid)
{
    for (int len = 2; len <= NF; len <<= 1) {
        int half  = len >> 1;
        int tstep = NF / len;
        for (int bi = tid; bi < NF/2; bi += 256) {
            int grp = bi / half;
            int pos = bi - grp*half;
            int i0 = grp*len + pos;
            int i1 = i0 + half;
            float2 w = tw[pos * tstep];
            float vr = re[i1], vi = im[i1];
            float tr = w.x*vr - w.y*vi;
            float ti = w.x*vi + w.y*vr;
            float ur = re[i0], ui = im[i0];
            re[i0] = ur + tr; im[i0] = ui + ti;
            re[i1] = ur - tr; im[i1] = ui - ti;
        }
        __syncthreads();
    }
}

// ============== 2a) rfft of k & v packed: z = k + i*v ======================
__global__ __launch_bounds__(256) void rfft_kv_kernel(
    const float* __restrict__ kin, const float* __restrict__ vin)
{
    __shared__ float  sre[NF], sim[NF];
    __shared__ float2 tw[NF/2];
    const int tid = threadIdx.x;
    const int bc  = blockIdx.x;              // b*512 + c
    for (int j = tid; j < NF/2; j += 256) {
        float s, c;
        sincosf(-6.283185307179586f * (float)j / (float)NF, &s, &c);
        tw[j] = make_float2(c, s);
    }
    const float* kp = kin + (size_t)(bc >> 9)*L_*D_ + (bc & 511);
    const float* vp = vin + (size_t)(bc >> 9)*L_*D_ + (bc & 511);
    for (int n = tid; n < NF; n += 256) {
        int r = __brev(n) >> 22;
        sre[r] = kp[(size_t)n * D_];
        sim[r] = vp[(size_t)n * D_];
    }
    __syncthreads();
    fft1024_smem(sre, sim, tw, tid);

    const float sc_ = 0.03125f;
    float2* kf = g_kf + (size_t)bc * LF;
    float2* vf = g_vf + (size_t)bc * LF;
    for (int x = tid; x < LF; x += 256) {
        int xm = (NF - x) & (NF - 1);
        float Pr = sre[x], Pi = sim[x], Qr = sre[xm], Qi = sim[xm];
        kf[x] = make_float2(0.5f*(Pr + Qr)*sc_, 0.5f*(Pi - Qi)*sc_);
        vf[x] = make_float2(0.5f*(Pi + Qi)*sc_, 0.5f*(Qr - Pr)*sc_);
    }
}

// ============== 2b) rfft of q2 packed channel pairs ========================
__global__ __launch_bounds__(256) void rfft_q_kernel()
{
    __shared__ float  sre[NF], sim[NF];
    __shared__ float2 tw[NF/2];
    const int tid = threadIdx.x;
    const int bc2 = blockIdx.x;              // b*256 + pair
    const int b   = bc2 >> 8;
    const int c0  = (bc2 & 255) * 2;
    for (int j = tid; j < NF/2; j += 256) {
        float s, c;
        sincosf(-6.283185307179586f * (float)j / (float)NF, &s, &c);
        tw[j] = make_float2(c, s);
    }
    const float* q0 = g_q2 + (size_t)b*L_*D_ + c0;
    for (int n = tid; n < NF; n += 256) {
        int r = __brev(n) >> 22;
        sre[r] = q0[(size_t)n * D_];
        sim[r] = q0[(size_t)n * D_ + 1];
    }
    __syncthreads();
    fft1024_smem(sre, sim, tw, tid);

    const float sc_ = 0.03125f;
    float2* f0 = g_qf + (size_t)(b*512 + c0) * LF;
    float2* f1 = f0 + LF;
    for (int x = tid; x < LF; x += 256) {
        int xm = (NF - x) & (NF - 1);
        float Pr = sre[x], Pi = sim[x], Qr = sre[xm], Qi = sim[xm];
        f0[x] = make_float2(0.5f*(Pr + Qr)*sc_, 0.5f*(Pi - Qi)*sc_);
        f1[x] = make_float2(0.5f*(Pi + Qi)*sc_, 0.5f*(Qr - Pr)*sc_);
    }
}

// ======================= 3) attention via mma.sync tf32 ====================
// Per (b,h): s = (qf^T conj(kf))/8;  g = 1.5 + 0.5*tanh(|s|/2);
// of = (sum_y s*g*vf) / max(sum_y |s|*g, 1e-12).
// Block: x-tile 64, loop y in 9 tiles of 64 (zero-padded past 513).
// Phase1: S[64x,64y] = Q[64x,64e] * K^T, complex via Kin=-Ki.
// Phase2: OF[64x,64e] += Sgated[64x,64y] * V^T, complex via Vin=-Vi.
struct AttnSmem2 {
    float Qr[64][68], Qi[64][68];           // [x][e]
    float Kr[64][68], Ki[64][68], Kin[64][68]; // [y][e]
    float Vr[64][68], Vi[64][68], Vin[64][68]; // [e][y]
    float Ssr[64][68], Ssi[64][68];         // [x][y], gated
    float rsum[64];
    float rinv[64];
};

__global__ __launch_bounds__(256) void attn_mma_kernel()
{
    extern __shared__ char sraw[];
    AttnSmem2& sm = *reinterpret_cast<AttnSmem2*>(sraw);
    const int tid  = threadIdx.x;
    const int wid  = tid >> 5;
    const int lane = tid & 31;
    const int gid  = lane >> 2;
    const int tg   = lane & 3;
    const int mw   = wid & 3;      // x quarter (16 rows)
    const int nw   = wid >> 2;     // y/e half (32 cols)
    const int xbase = blockIdx.x * 64;
    const int bh    = blockIdx.y;

    const float2* qf = g_qf + (size_t)bh * E_ * LF;
    const float2* kf = g_kf + (size_t)bh * E_ * LF;
    const float2* vf = g_vf + (size_t)bh * E_ * LF;
    float2*       of = g_of + (size_t)bh * E_ * LF;

    if (tid < 64) sm.rsum[tid] = 0.f;

    // Q tile: [e][x] gmem -> [x][e] smem, pre-scaled by 1/8
    for (int i = tid; i < 4096; i += 256) {
        int e = i >> 6, xx = i & 63;
        int x = xbase + xx;
        float2 v = make_float2(0.f, 0.f);
        if (x < LF) v = qf[(size_t)e*LF + x];
        sm.Qr[xx][e] = v.x * 0.125f;
        sm.Qi[xx][e] = v.y * 0.125f;
    }

    float ofr[4][4], ofi[4][4];
    #pragma unroll
    for (int j = 0; j < 4; ++j)
        #pragma unroll
        for (int u = 0; u < 4; ++u) { ofr[j][u] = 0.f; ofi[j][u] = 0.f; }
    float rs0 = 0.f, rs1 = 0.f;

    for (int yt = 0; yt < 9; ++yt) {
        const int ybase = yt * 64;
        __syncthreads();   // prev iter's phase2 done before K/V/Ss overwrite
        for (int i = tid; i < 4096; i += 256) {
            int e = i >> 6, yy = i & 63;
            int y = ybase + yy;
            float2 kv = make_float2(0.f, 0.f), vv = make_float2(0.f, 0.f);
            if (y < LF) { kv = kf[(size_t)e*LF + y]; vv = vf[(size_t)e*LF + y]; }
            sm.Kr[yy][e] = kv.x; sm.Ki[yy][e] = kv.y; sm.Kin[yy][e] = -kv.y;
            sm.Vr[e][yy] = vv.x; sm.Vi[e][yy] = vv.y; sm.Vin[e][yy] = -vv.y;
        }
        __syncthreads();

        // ---- phase 1: S = Q * conj(K)^T ----
        float Sr[4][4], Si[4][4];
        #pragma unroll
        for (int j = 0; j < 4; ++j)
            #pragma unroll
            for (int u = 0; u < 4; ++u) { Sr[j][u] = 0.f; Si[j][u] = 0.f; }

        #pragma unroll
        for (int k8 = 0; k8 < 8; ++k8) {
            uint32_t ar[4], ai[4];
            {
                const float* Qrp = &sm.Qr[mw*16 + gid][k8*8];
                const float* Qip = &sm.Qi[mw*16 + gid][k8*8];
                ar[0]=__float_as_uint(Qrp[tg]);      ar[1]=__float_as_uint(Qrp[8*68+tg]);
                ar[2]=__float_as_uint(Qrp[tg+4]);    ar[3]=__float_as_uint(Qrp[8*68+tg+4]);
                ai[0]=__float_as_uint(Qip[tg]);      ai[1]=__float_as_uint(Qip[8*68+tg]);
                ai[2]=__float_as_uint(Qip[tg+4]);    ai[3]=__float_as_uint(Qip[8*68+tg+4]);
            }
            #pragma unroll
            for (int j = 0; j < 4; ++j) {
                int nr = nw*32 + j*8 + gid;
                const float* Krp = &sm.Kr[nr][k8*8];
                const float* Kip = &sm.Ki[nr][k8*8];
                const float* Knp = &sm.Kin[nr][k8*8];
                uint32_t kr0=__float_as_uint(Krp[tg]), kr1=__float_as_uint(Krp[tg+4]);
                uint32_t ki0=__float_as_uint(Kip[tg]), ki1=__float_as_uint(Kip[tg+4]);
                uint32_t kn0=__float_as_uint(Knp[tg]), kn1=__float_as_uint(Knp[tg+4]);
                MMA_TF32(Sr[j], ar, kr0, kr1);
                MMA_TF32(Sr[j], ai, ki0, ki1);
                MMA_TF32(Si[j], ai, kr0, kr1);
                MMA_TF32(Si[j], ar, kn0, kn1);
            }
        }

        // ---- gating: g = 1.5 + 0.5*tanh(m/2); write S*g; rsum += m*g ----
        #pragma unroll
        for (int j = 0; j < 4; ++j) {
            #pragma unroll
            for (int h = 0; h < 2; ++h) {
                float re0 = Sr[j][h ? 2 : 0], im0 = Si[j][h ? 2 : 0];
                float re1 = Sr[j][h ? 3 : 1], im1 = Si[j][h ? 3 : 1];
                float m0 = sqrt_ap(fmaf(re0, re0, im0*im0));
                float m1 = sqrt_ap(fmaf(re1, re1, im1*im1));
                float g0 = fmaf(0.5f, tanh_ap(0.5f*m0), 1.5f);
                float g1 = fmaf(0.5f, tanh_ap(0.5f*m1), 1.5f);
                if (h) rs1 += fmaf(m0, g0, m1*g1); else rs0 += fmaf(m0, g0, m1*g1);
                int row = mw*16 + gid + h*8;
                int cb  = nw*32 + j*8 + 2*tg;
                *(float2*)&sm.Ssr[row][cb] = make_float2(re0*g0, re1*g1);
                *(float2*)&sm.Ssi[row][cb] = make_float2(im0*g0, im1*g1);
            }
        }
        __syncthreads();

        // ---- phase 2: OF += Sgated * V^T ----
        #pragma unroll
        for (int k8 = 0; k8 < 8; ++k8) {
            uint32_t asr[4], asi[4];
            {
                const float* Srp = &sm.Ssr[mw*16 + gid][k8*8];
                const float* Sip = &sm.Ssi[mw*16 + gid][k8*8];
                asr[0]=__float_as_uint(Srp[tg]);      asr[1]=__float_as_uint(Srp[8*68+tg]);
                asr[2]=__float_as_uint(Srp[tg+4]);    asr[3]=__float_as_uint(Srp[8*68+tg+4]);
                asi[0]=__float_as_uint(Sip[tg]);      asi[1]=__float_as_uint(Sip[8*68+tg]);
                asi[2]=__float_as_uint(Sip[tg+4]);    asi[3]=__float_as_uint(Sip[8*68+tg+4]);
            }
            #pragma unroll
            for (int j = 0; j < 4; ++j) {
                int nr = nw*32 + j*8 + gid;
                const float* Vrp = &sm.Vr[nr][k8*8];
                const float* Vip = &sm.Vi[nr][k8*8];
                const float* Vnp = &sm.Vin[nr][k8*8];
                uint32_t vr0=__float_as_uint(Vrp[tg]), vr1=__float_as_uint(Vrp[tg+4]);
                uint32_t vi0=__float_as_uint(Vip[tg]), vi1=__float_as_uint(Vip[tg+4]);
                uint32_t vn0=__float_as_uint(Vnp[tg]), vn1=__float_as_uint(Vnp[tg+4]);
                MMA_TF32(ofr[j], asr, vr0, vr1);
                MMA_TF32(ofr[j], asi, vn0, vn1);
                MMA_TF32(ofi[j], asr, vi0, vi1);
                MMA_TF32(ofi[j], asi, vr0, vr1);
            }
        }
    }

    // ---- rsum reduce: quad shfl + smem atomics ----
    rs0 += __shfl_xor_sync(0xFFFFFFFF, rs0, 1);
    rs0 += __shfl_xor_sync(0xFFFFFFFF, rs0, 2);
    rs1 += __shfl_xor_sync(0xFFFFFFFF, rs1, 1);
    rs1 += __shfl_xor_sync(0xFFFFFFFF, rs1, 2);
    if (tg == 0) {
        atomicAdd(&sm.rsum[mw*16 + gid],     rs0);
        atomicAdd(&sm.rsum[mw*16 + gid + 8], rs1);
    }
    __syncthreads();
    if (tid < 64) sm.rinv[tid] = 1.f / fmaxf(sm.rsum[tid], 1e-12f);
    __syncthreads();

    // ---- normalize + write of[e][x] ----
    #pragma unroll
    for (int j = 0; j < 4; ++j) {
        #pragma unroll
        for (int u = 0; u < 4; ++u) {
            int row = mw*16 + gid + ((u >= 2) ? 8 : 0);
            int e   = nw*32 + j*8 + 2*tg + (u & 1);
            int x   = xbase + row;
            if (x < LF) {
                float ri = sm.rinv[row];
                of[(size_t)e*LF + x] = make_float2(ofr[j][u]*ri, ofi[j][u]*ri);
            }
        }
    }
}

// ======================= 4) irfft packed channel pairs =====================
__global__ __launch_bounds__(256) void irfft_kernel(float* __restrict__ out)
{
    __shared__ float  sre[NF], sim[NF];
    __shared__ float2 tw[NF/2];
    const int tid = threadIdx.x;
    const int bc2 = blockIdx.x;              // b*256 + pair
    const int b   = bc2 >> 8;
    const int c0  = (bc2 & 255) * 2;
    const float2* o0 = g_of + (size_t)(b*512 + c0) * LF;
    const float2* o1 = o0 + LF;

    for (int j = tid; j < NF/2; j += 256) {
        float s, c;
        sincosf(-6.283185307179586f * (float)j / (float)NF, &s, &c);
        tw[j] = make_float2(c, s);
    }
    for (int n = tid; n < NF; n += 256) {
        int k2 = (n <= 512) ? n : NF - n;
        float sg = (n <= 512) ? 1.f : -1.f;
        float zf = (k2 == 0 || k2 == 512) ? 0.f : 1.f;
        float2 A0 = o0[k2], A1 = o1[k2];
        A0.y *= zf; A1.y *= zf;
        float cre = A0.x - sg * A1.y;
        float cim = -sg * A0.y - A1.x;
        int r = __brev(n) >> 22;
        sre[r] = cre; sim[r] = cim;
    }
    __syncthreads();
    fft1024_smem(sre, sim, tw, tid);

    float* op = out + (size_t)b*L_*D_ + c0;
    for (int n = tid; n < NF; n += 256) {
        op[(size_t)n * D_]     =  sre[n] * 0.03125f;
        op[(size_t)n * D_ + 1] = -sim[n] * 0.03125f;
    }
}

// ============================== launcher ===================================
extern "C" void kernel_launch(void* const* d_in, const int* in_sizes, int n_in,
                              void* d_out, int out_size)
{
    const float* q    = (const float*)d_in[0];
    const float* k    = (const float*)d_in[1];
    const float* v    = (const float*)d_in[2];
    const float* W    = (const float*)d_in[3];
    const float* bias = (const float*)d_in[4];
    float* out = (float*)d_out;

    float* q2p;
    cudaGetSymbolAddress((void**)&q2p, g_q2);

    cudaFuncSetAttribute(conv_mma_kernel,
        cudaFuncAttributeMaxDynamicSharedMemorySize, CONV_SMEM);
    cudaFuncSetAttribute(attn_mma_kernel,
        cudaFuncAttributeMaxDynamicSharedMemorySize, (int)sizeof(AttnSmem2));

    preround_kernel<<<4096, 256>>>(q, W);
    conv_mma_kernel<<<dim3(128, 8), 256, CONV_SMEM>>>(bias, q2p);
    rfft_kv_kernel<<<B_*D_, 256>>>(k, v);
    rfft_q_kernel<<<B_*256, 256>>>();
    attn_mma_kernel<<<dim3(9, B_*H_), 256, sizeof(AttnSmem2)>>>();
    irfft_kernel<<<B_*256, 256>>>(out);
}

// round 16
// speedup vs baseline: 2.1310x; 1.5325x over previous
#include <cuda_runtime.h>
#include <math.h>
#include <stdint.h>

#define B_  16
#define L_  1024
#define H_  8
#define E_  64
#define D_  512
#define LF  513
#define NF  1024
#define QN  (B_*L_*D_)
#define WN  (1024*512*3)

// ---------------- scratch (device globals; no allocations) ----------------
__device__ float  g_qr[QN];                  // tf32-rounded q
__device__ float  g_Wr[WN];                  // tf32-rounded W
__device__ float  g_q2[B_*L_*D_];            // conv+GLU output, [B,L,D]
__device__ float2 g_qf[B_*H_*E_*LF];
__device__ float2 g_kf[B_*H_*E_*LF];
__device__ float2 g_vf[B_*H_*E_*LF];
__device__ float2 g_of[B_*H_*E_*LF];

// ======================= helpers ==========================================
__device__ __forceinline__ uint32_t smem_u32(const void* p) {
    uint32_t a;
    asm("{ .reg .u64 t; cvta.to.shared.u64 t, %1; cvt.u32.u64 %0, t; }"
        : "=r"(a) : "l"(p));
    return a;
}
__device__ __forceinline__ float tf32r(float x) {   // round-to-nearest tf32
    float y; asm("cvt.rna.tf32.f32 %0, %1;" : "=f"(y) : "f"(x)); return y;
}
__device__ __forceinline__ float sqrt_ap(float x) {
    float y; asm("sqrt.approx.f32 %0, %1;" : "=f"(y) : "f"(x)); return y;
}
__device__ __forceinline__ float tanh_ap(float x) {
    float y; asm("tanh.approx.f32 %0, %1;" : "=f"(y) : "f"(x)); return y;
}

#define MMA_TF32(c, a, b0v, b1v) \
    asm volatile("mma.sync.aligned.m16n8k8.row.col.f32.tf32.tf32.f32 " \
        "{%0,%1,%2,%3}, {%4,%5,%6,%7}, {%8,%9}, {%0,%1,%2,%3};" \
        : "+f"((c)[0]), "+f"((c)[1]), "+f"((c)[2]), "+f"((c)[3]) \
        : "r"((a)[0]), "r"((a)[1]), "r"((a)[2]), "r"((a)[3]), \
          "r"(b0v), "r"(b1v))

// ======================= 0) pre-round q and W to tf32 ======================
__global__ __launch_bounds__(256) void preround_kernel(
    const float* __restrict__ q, const float* __restrict__ W)
{
    int i0 = blockIdx.x * blockDim.x + threadIdx.x;
    int stride = gridDim.x * blockDim.x;
    for (int i = i0; i < QN; i += stride) g_qr[i] = tf32r(q[i]);
    for (int i = i0; i < WN; i += stride) g_Wr[i] = tf32r(W[i]);
}

// ======================= 1) Conv1d+GLU via mma.sync tf32 ==================
#define CONV_SMEM (18432*4)

__global__ __launch_bounds__(256) void conv_mma_kernel(
    const float* __restrict__ bias, float* __restrict__ q2out)
{
    extern __shared__ float smf[];
    const int tid  = threadIdx.x;
    const int wid  = tid >> 5;
    const int lane = tid & 31;
    const int gid  = lane >> 2;          // 0..7
    const int tg   = lane & 3;           // 0..3
    const int mw   = wid & 3;            // 4 m-sections of 32
    const int nw   = wid >> 2;           // 2 n-sections of 64
    const int mtile = blockIdx.x;        // 0..127
    const int obase = blockIdx.y * 64;   // 0..448
    const int b  = mtile >> 3;
    const int l0 = (mtile & 7) * 128;
    const uint32_t sb = smem_u32(smf);
    const float* qb = g_qr + (size_t)b * L_ * D_;

    float C[2][8][4];
    #pragma unroll
    for (int mf = 0; mf < 2; ++mf)
        #pragma unroll
        for (int j = 0; j < 8; ++j)
            #pragma unroll
            for (int u = 0; u < 4; ++u) C[mf][j][u] = 0.f;

    auto issue = [&](int c, int bf) {
        #pragma unroll
        for (int j = 0; j < 16; ++j) {
            int linear = j * 256 + tid;
            int m  = linear & 127;
            int kk = linear >> 7;
            int k  = c * 32 + kk;
            int i  = k / 3;
            int t  = k - 3 * i;
            int lt = l0 + m + t - 1;
            int ltc = lt < 0 ? 0 : (lt > L_-1 ? L_-1 : lt);
            const float* src = qb + (size_t)ltc * D_ + i;
            int ss = (lt >= 0 && lt < L_) ? 4 : 0;
            uint32_t sa = sb + (uint32_t)(bf*4608 + m*36 + kk) * 4;
            asm volatile("cp.async.ca.shared.global [%0], [%1], 4, %2;"
                         :: "r"(sa), "l"(src), "r"(ss));
        }
        #pragma unroll
        for (int j = 0; j < 4; ++j) {
            int linear = j * 256 + tid;
            int n   = linear >> 3;
            int kk4 = linear & 7;
            int grow = ((n & 1) ? 512 : 0) + obase + (n >> 1);
            const float* src = g_Wr + (size_t)grow * 1536 + c * 32 + kk4 * 4;
            uint32_t sa = sb + (uint32_t)(9216 + bf*4608 + n*36 + kk4*4) * 4;
            asm volatile("cp.async.ca.shared.global [%0], [%1], 16, 16;"
                         :: "r"(sa), "l"(src));
        }
        asm volatile("cp.async.commit_group;");
    };

    issue(0, 0);
    for (int c = 0; c < 48; ++c) {
        const int bf = c & 1;
        if (c + 1 < 48) {
            issue(c + 1, bf ^ 1);
            asm volatile("cp.async.wait_group 1;");
        } else {
            asm volatile("cp.async.wait_group 0;");
        }
        __syncthreads();

        const float* Abase = smf + bf*4608;
        const float* Bbase = smf + 9216 + bf*4608;
        #pragma unroll
        for (int k8 = 0; k8 < 4; ++k8) {
            uint32_t af[2][4];
            #pragma unroll
            for (int mf = 0; mf < 2; ++mf) {
                const float* Ap = Abase + (mw*32 + mf*16 + gid)*36 + k8*8;
                af[mf][0] = __float_as_uint(Ap[tg]);
                af[mf][1] = __float_as_uint(Ap[8*36 + tg]);
                af[mf][2] = __float_as_uint(Ap[tg + 4]);
                af[mf][3] = __float_as_uint(Ap[8*36 + tg + 4]);
            }
            #pragma unroll
            for (int j = 0; j < 8; ++j) {
                const float* Bp = Bbase + (nw*64 + j*8 + gid)*36 + k8*8;
                uint32_t b0 = __float_as_uint(Bp[tg]);
                uint32_t b1 = __float_as_uint(Bp[tg + 4]);
                MMA_TF32(C[0][j], af[0], b0, b1);
                MMA_TF32(C[1][j], af[1], b0, b1);
            }
        }
        __syncthreads();
    }

    #pragma unroll
    for (int mf = 0; mf < 2; ++mf) {
        int r0 = mtile*128 + mw*32 + mf*16 + gid;
        #pragma unroll
        for (int j = 0; j < 8; ++j) {
            int och = obase + nw*32 + j*4 + tg;
            float ba = bias[och], bg = bias[512 + och];
            float a0 = C[mf][j][0] + ba, g0 = C[mf][j][1] + bg;
            float a1 = C[mf][j][2] + ba, g1 = C[mf][j][3] + bg;
            q2out[(size_t)r0*D_ + och]       = a0 / (1.f + __expf(-g0));
            q2out[(size_t)(r0+8)*D_ + och]   = a1 / (1.f + __expf(-g1));
        }
    }
}

// ======================= radix-2 FFT (1024-pt, smem) =======================
__device__ __forceinline__ void fft1024_smem(float* re, float* im,
                                             const float2* tw, int tid)
{
    for (int len = 2; len <= NF; len <<= 1) {
        int half  = len >> 1;
        int tstep = NF / len;
        for (int bi = tid; bi < NF/2; bi += 256) {
            int grp = bi / half;
            int pos = bi - grp*half;
            int i0 = grp*len + pos;
            int i1 = i0 + half;
            float2 w = tw[pos * tstep];
            float vr = re[i1], vi = im[i1];
            float tr = w.x*vr - w.y*vi;
            float ti = w.x*vi + w.y*vr;
            float ur = re[i0], ui = im[i0];
            re[i0] = ur + tr; im[i0] = ui + ti;
            re[i1] = ur - tr; im[i1] = ui - ti;
        }
        __syncthreads();
    }
}

// ============== 2a) rfft of k & v packed: z = k + i*v ======================
__global__ __launch_bounds__(256) void rfft_kv_kernel(
    const float* __restrict__ kin, const float* __restrict__ vin)
{
    __shared__ float  sre[NF], sim[NF];
    __shared__ float2 tw[NF/2];
    const int tid = threadIdx.x;
    const int bc  = blockIdx.x;              // b*512 + c
    for (int j = tid; j < NF/2; j += 256) {
        float s, c;
        sincosf(-6.283185307179586f * (float)j / (float)NF, &s, &c);
        tw[j] = make_float2(c, s);
    }
    const float* kp = kin + (size_t)(bc >> 9)*L_*D_ + (bc & 511);
    const float* vp = vin + (size_t)(bc >> 9)*L_*D_ + (bc & 511);
    for (int n = tid; n < NF; n += 256) {
        int r = __brev(n) >> 22;
        sre[r] = kp[(size_t)n * D_];
        sim[r] = vp[(size_t)n * D_];
    }
    __syncthreads();
    fft1024_smem(sre, sim, tw, tid);

    const float sc_ = 0.03125f;
    float2* kf = g_kf + (size_t)bc * LF;
    float2* vf = g_vf + (size_t)bc * LF;
    for (int x = tid; x < LF; x += 256) {
        int xm = (NF - x) & (NF - 1);
        float Pr = sre[x], Pi = sim[x], Qr = sre[xm], Qi = sim[xm];
        kf[x] = make_float2(0.5f*(Pr + Qr)*sc_, 0.5f*(Pi - Qi)*sc_);
        vf[x] = make_float2(0.5f*(Pi + Qi)*sc_, 0.5f*(Qr - Pr)*sc_);
    }
}

// ============== 2b) rfft of q2 packed channel pairs ========================
__global__ __launch_bounds__(256) void rfft_q_kernel()
{
    __shared__ float  sre[NF], sim[NF];
    __shared__ float2 tw[NF/2];
    const int tid = threadIdx.x;
    const int bc2 = blockIdx.x;              // b*256 + pair
    const int b   = bc2 >> 8;
    const int c0  = (bc2 & 255) * 2;
    for (int j = tid; j < NF/2; j += 256) {
        float s, c;
        sincosf(-6.283185307179586f * (float)j / (float)NF, &s, &c);
        tw[j] = make_float2(c, s);
    }
    const float* q0 = g_q2 + (size_t)b*L_*D_ + c0;
    for (int n = tid; n < NF; n += 256) {
        int r = __brev(n) >> 22;
        sre[r] = q0[(size_t)n * D_];
        sim[r] = q0[(size_t)n * D_ + 1];
    }
    __syncthreads();
    fft1024_smem(sre, sim, tw, tid);

    const float sc_ = 0.03125f;
    float2* f0 = g_qf + (size_t)(b*512 + c0) * LF;
    float2* f1 = f0 + LF;
    for (int x = tid; x < LF; x += 256) {
        int xm = (NF - x) & (NF - 1);
        float Pr = sre[x], Pi = sim[x], Qr = sre[xm], Qi = sim[xm];
        f0[x] = make_float2(0.5f*(Pr + Qr)*sc_, 0.5f*(Pi - Qi)*sc_);
        f1[x] = make_float2(0.5f*(Pi + Qi)*sc_, 0.5f*(Qr - Pr)*sc_);
    }
}

// ======================= 3) attention via mma.sync tf32 ====================
// s = (qf^T conj(kf))/8;  g = 1.5 + 0.5*tanh(|s|/2);
// of = (sum_y s*g*vf) / max(sum_y |s|*g, 1e-12).
struct AttnSmem2 {
    float Qr[64][68], Qi[64][68];           // [x][e]
    float Kr[64][68], Ki[64][68], Kin[64][68]; // [y][e]
    float Vr[64][68], Vi[64][68], Vin[64][68]; // [e][y]
    float Ssr[64][68], Ssi[64][68];         // [x][y], gated
    float rsum[64];
    float rinv[64];
};

__global__ __launch_bounds__(256) void attn_mma_kernel()
{
    extern __shared__ char sraw[];
    AttnSmem2& sm = *reinterpret_cast<AttnSmem2*>(sraw);
    const int tid  = threadIdx.x;
    const int wid  = tid >> 5;
    const int lane = tid & 31;
    const int gid  = lane >> 2;
    const int tg   = lane & 3;
    const int mw   = wid & 3;      // x quarter (16 rows)
    const int nw   = wid >> 2;     // y/e half (32 cols)
    const int xbase = blockIdx.x * 64;
    const int bh    = blockIdx.y;

    const float2* qf = g_qf + (size_t)bh * E_ * LF;
    const float2* kf = g_kf + (size_t)bh * E_ * LF;
    const float2* vf = g_vf + (size_t)bh * E_ * LF;
    float2*       of = g_of + (size_t)bh * E_ * LF;

    if (tid < 64) sm.rsum[tid] = 0.f;

    // Q tile: [e][x] gmem -> [x][e] smem, pre-scaled by 1/8
    for (int i = tid; i < 4096; i += 256) {
        int e = i >> 6, xx = i & 63;
        int x = xbase + xx;
        float2 v = make_float2(0.f, 0.f);
        if (x < LF) v = qf[(size_t)e*LF + x];
        sm.Qr[xx][e] = v.x * 0.125f;
        sm.Qi[xx][e] = v.y * 0.125f;
    }

    float ofr[4][4], ofi[4][4];
    #pragma unroll
    for (int j = 0; j < 4; ++j)
        #pragma unroll
        for (int u = 0; u < 4; ++u) { ofr[j][u] = 0.f; ofi[j][u] = 0.f; }
    float rs0 = 0.f, rs1 = 0.f;

    for (int yt = 0; yt < 9; ++yt) {
        const int ybase = yt * 64;
        __syncthreads();   // prev iter's phase2 done before K/V/Ss overwrite
        for (int i = tid; i < 4096; i += 256) {
            int e = i >> 6, yy = i & 63;
            int y = ybase + yy;
            float2 kv = make_float2(0.f, 0.f), vv = make_float2(0.f, 0.f);
            if (y < LF) { kv = kf[(size_t)e*LF + y]; vv = vf[(size_t)e*LF + y]; }
            sm.Kr[yy][e] = kv.x; sm.Ki[yy][e] = kv.y; sm.Kin[yy][e] = -kv.y;
            sm.Vr[e][yy] = vv.x; sm.Vi[e][yy] = vv.y; sm.Vin[e][yy] = -vv.y;
        }
        __syncthreads();

        // ---- phase 1: S = Q * conj(K)^T ----
        float Sr[4][4], Si[4][4];
        #pragma unroll
        for (int j = 0; j < 4; ++j)
            #pragma unroll
            for (int u = 0; u < 4; ++u) { Sr[j][u] = 0.f; Si[j][u] = 0.f; }

        #pragma unroll
        for (int k8 = 0; k8 < 8; ++k8) {
            uint32_t ar[4], ai[4];
            {
                const float* Qrp = &sm.Qr[mw*16 + gid][k8*8];
                const float* Qip = &sm.Qi[mw*16 + gid][k8*8];
                ar[0]=__float_as_uint(Qrp[tg]);      ar[1]=__float_as_uint(Qrp[8*68+tg]);
                ar[2]=__float_as_uint(Qrp[tg+4]);    ar[3]=__float_as_uint(Qrp[8*68+tg+4]);
                ai[0]=__float_as_uint(Qip[tg]);      ai[1]=__float_as_uint(Qip[8*68+tg]);
                ai[2]=__float_as_uint(Qip[tg+4]);    ai[3]=__float_as_uint(Qip[8*68+tg+4]);
            }
            #pragma unroll
            for (int j = 0; j < 4; ++j) {
                int nr = nw*32 + j*8 + gid;
                const float* Krp = &sm.Kr[nr][k8*8];
                const float* Kip = &sm.Ki[nr][k8*8];
                const float* Knp = &sm.Kin[nr][k8*8];
                uint32_t kr0=__float_as_uint(Krp[tg]), kr1=__float_as_uint(Krp[tg+4]);
                uint32_t ki0=__float_as_uint(Kip[tg]), ki1=__float_as_uint(Kip[tg+4]);
                uint32_t kn0=__float_as_uint(Knp[tg]), kn1=__float_as_uint(Knp[tg+4]);
                MMA_TF32(Sr[j], ar, kr0, kr1);
                MMA_TF32(Sr[j], ai, ki0, ki1);
                MMA_TF32(Si[j], ai, kr0, kr1);
                MMA_TF32(Si[j], ar, kn0, kn1);
            }
        }

        // ---- gating: g = 1.5 + 0.5*tanh(m/2); write S*g; rsum += m*g ----
        #pragma unroll
        for (int j = 0; j < 4; ++j) {
            #pragma unroll
            for (int h = 0; h < 2; ++h) {
                float re0 = Sr[j][h ? 2 : 0], im0 = Si[j][h ? 2 : 0];
                float re1 = Sr[j][h ? 3 : 1], im1 = Si[j][h ? 3 : 1];
                float m0 = sqrt_ap(fmaf(re0, re0, im0*im0));
                float m1 = sqrt_ap(fmaf(re1, re1, im1*im1));
                float g0 = fmaf(0.5f, tanh_ap(0.5f*m0), 1.5f);
                float g1 = fmaf(0.5f, tanh_ap(0.5f*m1), 1.5f);
                if (h) rs1 += fmaf(m0, g0, m1*g1); else rs0 += fmaf(m0, g0, m1*g1);
                int row = mw*16 + gid + h*8;
                int cb  = nw*32 + j*8 + 2*tg;
                *(float2*)&sm.Ssr[row][cb] = make_float2(re0*g0, re1*g1);
                *(float2*)&sm.Ssi[row][cb] = make_float2(im0*g0, im1*g1);
            }
        }
        __syncthreads();

        // ---- phase 2: OF += Sgated * V^T ----
        #pragma unroll
        for (int k8 = 0; k8 < 8; ++k8) {
            uint32_t asr[4], asi[4];
            {
                const float* Srp = &sm.Ssr[mw*16 + gid][k8*8];
                const float* Sip = &sm.Ssi[mw*16 + gid][k8*8];
                asr[0]=__float_as_uint(Srp[tg]);      asr[1]=__float_as_uint(Srp[8*68+tg]);
                asr[2]=__float_as_uint(Srp[tg+4]);    asr[3]=__float_as_uint(Srp[8*68+tg+4]);
                asi[0]=__float_as_uint(Sip[tg]);      asi[1]=__float_as_uint(Sip[8*68+tg]);
                asi[2]=__float_as_uint(Sip[tg+4]);    asi[3]=__float_as_uint(Sip[8*68+tg+4]);
            }
            #pragma unroll
            for (int j = 0; j < 4; ++j) {
                int nr = nw*32 + j*8 + gid;
                const float* Vrp = &sm.Vr[nr][k8*8];
                const float* Vip = &sm.Vi[nr][k8*8];
                const float* Vnp = &sm.Vin[nr][k8*8];
                uint32_t vr0=__float_as_uint(Vrp[tg]), vr1=__float_as_uint(Vrp[tg+4]);
                uint32_t vi0=__float_as_uint(Vip[tg]), vi1=__float_as_uint(Vip[tg+4]);
                uint32_t vn0=__float_as_uint(Vnp[tg]), vn1=__float_as_uint(Vnp[tg+4]);
                MMA_TF32(ofr[j], asr, vr0, vr1);
                MMA_TF32(ofr[j], asi, vn0, vn1);
                MMA_TF32(ofi[j], asr, vi0, vi1);
                MMA_TF32(ofi[j], asi, vr0, vr1);
            }
        }
    }

    // ---- rsum reduce: quad shfl + smem atomics ----
    rs0 += __shfl_xor_sync(0xFFFFFFFF, rs0, 1);
    rs0 += __shfl_xor_sync(0xFFFFFFFF, rs0, 2);
    rs1 += __shfl_xor_sync(0xFFFFFFFF, rs1, 1);
    rs1 += __shfl_xor_sync(0xFFFFFFFF, rs1, 2);
    if (tg == 0) {
        atomicAdd(&sm.rsum[mw*16 + gid],     rs0);
        atomicAdd(&sm.rsum[mw*16 + gid + 8], rs1);
    }
    __syncthreads();
    if (tid < 64) sm.rinv[tid] = 1.f / fmaxf(sm.rsum[tid], 1e-12f);
    __syncthreads();

    // ---- normalize + write of[e][x] ----
    #pragma unroll
    for (int j = 0; j < 4; ++j) {
        #pragma unroll
        for (int u = 0; u < 4; ++u) {
            int row = mw*16 + gid + ((u >= 2) ? 8 : 0);
            int e   = nw*32 + j*8 + 2*tg + (u & 1);
            int x   = xbase + row;
            if (x < LF) {
                float ri = sm.rinv[row];
                of[(size_t)e*LF + x] = make_float2(ofr[j][u]*ri, ofi[j][u]*ri);
            }
        }
    }
}

// ======================= 4) irfft packed channel pairs =====================
__global__ __launch_bounds__(256) void irfft_kernel(float* __restrict__ out)
{
    __shared__ float  sre[NF], sim[NF];
    __shared__ float2 tw[NF/2];
    const int tid = threadIdx.x;
    const int bc2 = blockIdx.x;              // b*256 + pair
    const int b   = bc2 >> 8;
    const int c0  = (bc2 & 255) * 2;
    const float2* o0 = g_of + (size_t)(b*512 + c0) * LF;
    const float2* o1 = o0 + LF;

    for (int j = tid; j < NF/2; j += 256) {
        float s, c;
        sincosf(-6.283185307179586f * (float)j / (float)NF, &s, &c);
        tw[j] = make_float2(c, s);
    }
    for (int n = tid; n < NF; n += 256) {
        int k2 = (n <= 512) ? n : NF - n;
        float sg = (n <= 512) ? 1.f : -1.f;
        float zf = (k2 == 0 || k2 == 512) ? 0.f : 1.f;
        float2 A0 = o0[k2], A1 = o1[k2];
        A0.y *= zf; A1.y *= zf;
        float cre = A0.x - sg * A1.y;
        float cim = -sg * A0.y - A1.x;
        int r = __brev(n) >> 22;
        sre[r] = cre; sim[r] = cim;
    }
    __syncthreads();
    fft1024_smem(sre, sim, tw, tid);

    float* op = out + (size_t)b*L_*D_ + c0;
    for (int n = tid; n < NF; n += 256) {
        op[(size_t)n * D_]     =  sre[n] * 0.03125f;
        op[(size_t)n * D_ + 1] = -sim[n] * 0.03125f;
    }
}

// ============================== launcher ===================================
extern "C" void kernel_launch(void* const* d_in, const int* in_sizes, int n_in,
                              void* d_out, int out_size)
{
    const float* q    = (const float*)d_in[0];
    const float* k    = (const float*)d_in[1];
    const float* v    = (const float*)d_in[2];
    const float* W    = (const float*)d_in[3];
    const float* bias = (const float*)d_in[4];
    float* out = (float*)d_out;

    float* q2p;
    cudaGetSymbolAddress((void**)&q2p, g_q2);

    cudaFuncSetAttribute(conv_mma_kernel,
        cudaFuncAttributeMaxDynamicSharedMemorySize, CONV_SMEM);
    cudaFuncSetAttribute(attn_mma_kernel,
        cudaFuncAttributeMaxDynamicSharedMemorySize, (int)sizeof(AttnSmem2));

    preround_kernel<<<4096, 256>>>(q, W);
    conv_mma_kernel<<<dim3(128, 8), 256, CONV_SMEM>>>(bias, q2p);
    rfft_kv_kernel<<<B_*D_, 256>>>(k, v);
    rfft_q_kernel<<<B_*256, 256>>>();
    attn_mma_kernel<<<dim3(9, B_*H_), 256, sizeof(AttnSmem2)>>>();
    irfft_kernel<<<B_*256, 256>>>(out);
}